// round 13
// baseline (speedup 1.0000x reference)
#include <cuda_runtime.h>
#include <cuda_bf16.h>
#include <math.h>
#include <stdint.h>

// Problem constants
#define BB 128     // batch
#define SS 256     // seq len
#define DD 512     // embed dim
#define HH 1024    // hidden
#define NCC 128    // num classes
#define NCLS 129   // embedding rows

// Recurrence config
#define RGRID 128      // persistent CTAs, each owns 8 h-cols (32 gate-cols)
#define RTHREADS 256   // 8 warps: two split-K halves of 4 warps each
#define HCPC 8         // h-cols per CTA
#define NCPC 32        // gate-cols per CTA
#define HROW 2048      // bytes per h row (1024 bf16)

// SMEM: 16 resident weight tiles (32n x 64k bf16, 4KB, SW128)
//       6 A tiles (3 per k-half, 16KB each); D buffers (2 x 128 x 36 fp32) overlap A
#define W_TILE  4096
#define W_BYTES (16 * W_TILE)
#define A_TILE  16384
#define D_ROW   144
#define DBUF    (128 * D_ROW)
#define SMEM_DYN (W_BYTES + 6 * A_TILE + 1024)

#define SWZ(o) ((o) ^ (((o) >> 3) & 0x70))

// ---------------- device scratch ----------------
__device__ float d_P[(size_t)NCLS * HH * 4];     // P[class][col][gate]
__device__ float d_Wp[(size_t)HH * HH * 4];      // Wp[k][col][gate] fp32
__device__ int   d_xT[SS * BB];                  // x transposed [t][b]
__device__ __nv_bfloat16 d_hbf[2][BB * HH];      // h double buffer, [b][k] bf16
__device__ float d_hfin[BB * HH];                // final-step h fp32 [b][k]
__device__ volatile unsigned d_stepf[RGRID];     // per-CTA step flags (monotonic)

// ---------------- helpers ----------------
__device__ __forceinline__ uint32_t smem_u32(const void* p) {
    uint32_t a;
    asm("{ .reg .u64 t; cvta.to.shared.u64 t, %1; cvt.u32.u64 %0, t; }" : "=r"(a) : "l"(p));
    return a;
}
__device__ __forceinline__ void ldsm4(uint32_t& r0, uint32_t& r1, uint32_t& r2, uint32_t& r3,
                                      uint32_t addr) {
    asm volatile("ldmatrix.sync.aligned.m8n8.x4.shared.b16 {%0,%1,%2,%3}, [%4];"
                 : "=r"(r0), "=r"(r1), "=r"(r2), "=r"(r3) : "r"(addr));
}
__device__ __forceinline__ void mma16816(float* d, const uint32_t* a, uint32_t b0, uint32_t b1) {
    asm volatile("mma.sync.aligned.m16n8k16.row.col.f32.bf16.bf16.f32 "
                 "{%0,%1,%2,%3}, {%4,%5,%6,%7}, {%8,%9}, {%0,%1,%2,%3};"
                 : "+f"(d[0]), "+f"(d[1]), "+f"(d[2]), "+f"(d[3])
                 : "r"(a[0]), "r"(a[1]), "r"(a[2]), "r"(a[3]), "r"(b0), "r"(b1));
}
__device__ __forceinline__ float sigf(float x) {
    float e = __expf(-x);
    return __fdividef(1.0f, 1.0f + e);
}
__device__ __forceinline__ float tanh_s(float x) {
    float a = fabsf(x);
    float e = __expf(-2.0f * a);
    float r = __fdividef(1.0f - e, 1.0f + e);
    return copysignf(r, x);
}

// load one A tile (h k-block kt: 128 rows x 64 bf16) into SMEM at dst (SW128);
// executed by the 128 threads of one k-half (gtid = 0..127)
__device__ __forceinline__ void load_tile(const char* hsrc, int kt, uint32_t dst, int gtid) {
#pragma unroll
    for (int j = 0; j < 8; j++) {
        const int g   = gtid + j * 128;           // 0..1023
        const int row = g >> 3, c16 = g & 7;
        const char* s = hsrc + (size_t)row * HROW + (size_t)kt * 128 + c16 * 16;
        uint32_t d = dst + SWZ((unsigned)(row * 128 + c16 * 16));
        asm volatile("cp.async.cg.shared.global [%0], [%1], 16;" :: "r"(d), "l"(s));
    }
}

// ---------------- prep kernels ----------------
__global__ void k_misc(const int* __restrict__ x) {
    int i = blockIdx.x * 256 + threadIdx.x;
    if (i < BB * HH / 2) ((uint32_t*)d_hbf)[i] = 0u;   // zero bf16 h buffer 0
    if (i < RGRID) d_stepf[i] = 0u;
    if (i < SS * BB) {
        int t = i >> 7, b = i & 127;
        d_xT[i] = x[b * SS + t];
    }
}

__global__ void k_pack(const float* __restrict__ Wfh, const float* __restrict__ Wih,
                       const float* __restrict__ Wgh, const float* __restrict__ Woh) {
    int i = blockIdx.x * 256 + threadIdx.x;
    if (i < HH * HH) {
        float4 v = make_float4(Wfh[i], Wih[i], Wgh[i], Woh[i]);
        *(float4*)(d_Wp + 4 * (size_t)i) = v;
    }
}

__global__ void k_precomp(const float* __restrict__ emb,
                          const float* __restrict__ Wfx, const float* __restrict__ Wix,
                          const float* __restrict__ Wgx, const float* __restrict__ Wox,
                          const float* __restrict__ bfv, const float* __restrict__ biv,
                          const float* __restrict__ bgv, const float* __restrict__ bov) {
    __shared__ float es[16][32];
    const int tid = threadIdx.x;
    const int col = blockIdx.x * 128 + tid;
    const int c0  = blockIdx.y * 16;

    float acc[16][4];
#pragma unroll
    for (int ci = 0; ci < 16; ci++)
#pragma unroll
        for (int g = 0; g < 4; g++) acc[ci][g] = 0.0f;

    for (int k0 = 0; k0 < DD; k0 += 32) {
        for (int q = tid; q < 16 * 32; q += 128) {
            int ci = q >> 5, kk = q & 31;
            int c = c0 + ci;
            es[ci][kk] = (c < NCLS) ? emb[(size_t)c * DD + k0 + kk] : 0.0f;
        }
        __syncthreads();
#pragma unroll 4
        for (int kk = 0; kk < 32; kk++) {
            int d = k0 + kk;
            float wf = Wfx[(size_t)d * HH + col];
            float wi = Wix[(size_t)d * HH + col];
            float wg = Wgx[(size_t)d * HH + col];
            float wo = Wox[(size_t)d * HH + col];
#pragma unroll
            for (int ci = 0; ci < 16; ci++) {
                float e = es[ci][kk];
                acc[ci][0] = fmaf(e, wf, acc[ci][0]);
                acc[ci][1] = fmaf(e, wi, acc[ci][1]);
                acc[ci][2] = fmaf(e, wg, acc[ci][2]);
                acc[ci][3] = fmaf(e, wo, acc[ci][3]);
            }
        }
        __syncthreads();
    }
    float b0v = bfv[col], b1v = biv[col], b2v = bgv[col], b3v = bov[col];
#pragma unroll
    for (int ci = 0; ci < 16; ci++) {
        int c = c0 + ci;
        if (c < NCLS) {
            float4 v = make_float4(acc[ci][0] + b0v, acc[ci][1] + b1v,
                                   acc[ci][2] + b2v, acc[ci][3] + b3v);
            *(float4*)(d_P + ((size_t)c * HH + col) * 4) = v;
        }
    }
}

// ---------------- persistent mma.sync recurrence (128 CTAs, split-K, 8 warps) ----------------
// CTA owns 32 gate-cols (8 h-cols). Weights SMEM-resident bf16 (SW128 tiles, 64KB).
// Warps 0-3: k in [0,512); warps 4-7: k in [512,1024). Warp tile m64 x n16.
// Partial D sums in two SMEM buffers; 256-thread epilogue sums them.
// Grid barrier = distributed per-CTA flags (no contended atomics).
__global__ void __launch_bounds__(RTHREADS, 1) k_recur() {
    extern __shared__ __align__(16) char dsm[];
    const int tid  = threadIdx.x;
    const int wid  = tid >> 5;
    const int lane = tid & 31;
    const int cta  = blockIdx.x;
    const int kw   = wid >> 2;        // 0..1 : k-half
    const int mw   = (wid >> 1) & 1;  // m64 half
    const int nw   = wid & 1;         // n16 half
    const int gtid = tid & 127;       // thread id within k-half

    uint32_t smem0 = smem_u32(dsm);
    uint32_t base  = (smem0 + 1023u) & ~1023u;
    char* dsb = dsm + (base - smem0);
    const uint32_t Wb = base;
    const uint32_t Ab = base + W_BYTES;
    char* dptr = dsb + W_BYTES;       // D buffers overlap A region (96KB >= 36KB)

    // ---- resident weights: tile q = k-block [64q, 64q+64); rows n=0..31, SW128
    for (int q = 0; q < 16; q++) {
        const float* src = d_Wp + (size_t)q * 64 * (HH * 4) + cta * NCPC;
        char* tile = dsb + q * W_TILE;
        for (int i2 = tid; i2 < 2048; i2 += RTHREADS) {
            int n = i2 & 31, kk = i2 >> 5;
            *(__nv_bfloat16*)(tile + SWZ((unsigned)(n * 128 + kk * 2))) =
                __float2bfloat16(src[(size_t)kk * (HH * 4) + n]);
        }
    }
    __syncthreads();

    // ---- lane-constant ldmatrix address pieces
    const int grp = lane >> 3, r8 = lane & 7;
    uint32_t a_row[4], a_xor[4];
#pragma unroll
    for (int mt = 0; mt < 4; mt++) {
        int m = 64 * mw + 16 * mt + (grp & 1) * 8 + r8;
        a_row[mt] = (uint32_t)(m * 128);
        a_xor[mt] = (uint32_t)((m & 7) * 16);
    }
    const int cgA = grp >> 1;
    // B: one ldsm.x4 per kc covers n16 x k16
    const int nB = 16 * nw + (grp >> 1) * 8 + r8;
    const uint32_t b_row = (uint32_t)(nB * 128);
    const uint32_t b_xor = (uint32_t)((nB & 7) * 16);
    const int cgB = grp & 1;

    // epilogue ownership: b = tid&127, col-quad = tid>>7 (4 cols each)
    const int eb   = tid & 127;
    const int ehal = tid >> 7;

    const int tb = kw * 3;            // A-buffer base index for this k-half
    const int barid = 1 + kw;

    float C[4];
#pragma unroll
    for (int c = 0; c < 4; c++) C[c] = 0.0f;

    for (int t = 0; t < SS; t++) {
        const char* hsrc = (const char*)d_hbf[t & 1];

        // prefetch epilogue operands (known at step start) to hide L2 latency
        const int cls = d_xT[t * BB + eb];
        const float4* PpG = (const float4*)(d_P + ((size_t)cls * HH + cta * HCPC + ehal * 4) * 4);
        float4 pg0 = PpG[0], pg1 = PpG[1], pg2 = PpG[2], pg3 = PpG[3];

        // preload this half's first two k-tiles
        load_tile(hsrc, 8 * kw + 0, Ab + (tb + 0) * A_TILE, gtid);
        asm volatile("cp.async.commit_group;");
        load_tile(hsrc, 8 * kw + 1, Ab + (tb + 1) * A_TILE, gtid);
        asm volatile("cp.async.commit_group;");

        float acc[4][2][4];
#pragma unroll
        for (int mt = 0; mt < 4; mt++)
#pragma unroll
            for (int nt = 0; nt < 2; nt++)
#pragma unroll
                for (int e = 0; e < 4; e++) acc[mt][nt][e] = 0.0f;

        for (int i = 0; i < 8; i++) {
            if (i < 7) asm volatile("cp.async.wait_group 1;");
            else       asm volatile("cp.async.wait_group 0;");
            asm volatile("bar.sync %0, %1;" :: "r"(barid), "r"(128) : "memory");
            if (i < 6) {
                load_tile(hsrc, 8 * kw + i + 2, Ab + (tb + (i + 2) % 3) * A_TILE, gtid);
                asm volatile("cp.async.commit_group;");
            }
            const uint32_t Abuf  = Ab + (tb + i % 3) * A_TILE;
            const uint32_t Wtile = Wb + (8 * kw + i) * W_TILE;
#pragma unroll
            for (int kc = 0; kc < 4; kc++) {
                uint32_t a[4][4];
#pragma unroll
                for (int mt = 0; mt < 4; mt++)
                    ldsm4(a[mt][0], a[mt][1], a[mt][2], a[mt][3],
                          Abuf + a_row[mt] + (((unsigned)(16 * (2 * kc + cgA))) ^ a_xor[mt]));
                uint32_t bf[4];
                ldsm4(bf[0], bf[1], bf[2], bf[3],
                      Wtile + b_row + (((unsigned)(16 * (2 * kc + cgB))) ^ b_xor));
#pragma unroll
                for (int mt = 0; mt < 4; mt++) {
                    mma16816(acc[mt][0], a[mt], bf[0], bf[1]);
                    mma16816(acc[mt][1], a[mt], bf[2], bf[3]);
                }
            }
        }

        // full sync: no D write may start while any half still reads its A buffers
        __syncthreads();

        // ---- partial D -> SMEM (per k-half buffer)
        char* dD = dptr + kw * DBUF;
#pragma unroll
        for (int mt = 0; mt < 4; mt++) {
#pragma unroll
            for (int nt = 0; nt < 2; nt++) {
                int r0 = 64 * mw + 16 * mt + (lane >> 2);
                int cc = 16 * nw + 8 * nt + 2 * (lane & 3);
                *(float2*)(dD + r0 * D_ROW + cc * 4) =
                    make_float2(acc[mt][nt][0], acc[mt][nt][1]);
                *(float2*)(dD + (r0 + 8) * D_ROW + cc * 4) =
                    make_float2(acc[mt][nt][2], acc[mt][nt][3]);
            }
        }
        __syncthreads();

        // ---- epilogue: thread = (batch row, col-quad); sums both k-half partials
        const char* drow = dptr + eb * D_ROW + ehal * 64;
        __nv_bfloat16 hb16[4];
        float4 pg[4] = {pg0, pg1, pg2, pg3};
#pragma unroll
        for (int c = 0; c < 4; c++) {
            float4 d0 = *(const float4*)(drow + c * 16);
            float4 d1 = *(const float4*)(drow + DBUF + c * 16);
            float f  = sigf(d0.x + d1.x + pg[c].x);
            float ii = sigf(d0.y + d1.y + pg[c].y);
            float gg = sigf(d0.z + d1.z + pg[c].z);
            float oo = sigf(d0.w + d1.w + pg[c].w);
            float Cn = fmaf(gg, ii, C[c] * f);
            Cn = (cls > 0) ? Cn : 0.0f;
            C[c] = Cn;
            float hv = oo * tanh_s(Cn);
            hb16[c] = __float2bfloat16(hv);
            if (t == SS - 1) d_hfin[(size_t)eb * HH + cta * HCPC + ehal * 4 + c] = hv;
        }
        __nv_bfloat16* hd = d_hbf[(t + 1) & 1] + (size_t)eb * HH + cta * HCPC + ehal * 4;
        *(uint2*)hd = *(uint2*)&hb16[0];

        // ---- distributed-flag grid barrier
        __threadfence();
        __syncthreads();
        if (tid == 0) d_stepf[cta] = (unsigned)(t + 1);
        if (tid < RGRID) {
            while (d_stepf[tid] < (unsigned)(t + 1)) { }
        }
        __syncthreads();
    }
}

// ---------------- head ----------------
__global__ void k_head(const float* __restrict__ Wph, const float* __restrict__ bp,
                       float* __restrict__ out) {
    __shared__ float h_s[HH];
    __shared__ float red[128];
    const int b = blockIdx.x;
    const int n = threadIdx.x;

    for (int i = n; i < HH; i += 128) h_s[i] = d_hfin[(size_t)b * HH + i];
    __syncthreads();

    float p = bp[n];
#pragma unroll 8
    for (int k = 0; k < HH; k++) p = fmaf(h_s[k], Wph[(size_t)k * NCC + n], p);

    red[n] = p;
    __syncthreads();
    for (int s = 64; s > 0; s >>= 1) {
        if (n < s) red[n] = fmaxf(red[n], red[n + s]);
        __syncthreads();
    }
    float mx = red[0];
    __syncthreads();
    red[n] = __expf(p - mx);
    __syncthreads();
    for (int s = 64; s > 0; s >>= 1) {
        if (n < s) red[n] += red[n + s];
        __syncthreads();
    }
    float lse = mx + logf(red[0]);
    out[(size_t)b * NCC + n] = p - lse;
}

// ---------------- launch ----------------
extern "C" void kernel_launch(void* const* d_in, const int* in_sizes, int n_in,
                              void* d_out, int out_size) {
    const int*   x   = (const int*)d_in[0];
    const float* emb = (const float*)d_in[1];
    const float* Wfx = (const float*)d_in[2];
    const float* Wfh = (const float*)d_in[3];
    const float* bf  = (const float*)d_in[4];
    const float* Wix = (const float*)d_in[5];
    const float* Wih = (const float*)d_in[6];
    const float* bi  = (const float*)d_in[7];
    const float* Wgx = (const float*)d_in[8];
    const float* Wgh = (const float*)d_in[9];
    const float* bg  = (const float*)d_in[10];
    const float* Wox = (const float*)d_in[11];
    const float* Woh = (const float*)d_in[12];
    const float* bo  = (const float*)d_in[13];
    const float* Wph = (const float*)d_in[14];
    const float* bp  = (const float*)d_in[15];
    float* out = (float*)d_out;

    cudaFuncSetAttribute(k_recur, cudaFuncAttributeMaxDynamicSharedMemorySize, SMEM_DYN);

    k_misc<<<512, 256>>>(x);
    k_pack<<<(HH * HH + 255) / 256, 256>>>(Wfh, Wih, Wgh, Woh);
    dim3 gP(8, 9);
    k_precomp<<<gP, 128>>>(emb, Wfx, Wix, Wgx, Wox, bf, bi, bg, bo);
    k_recur<<<RGRID, RTHREADS, SMEM_DYN>>>();
    k_head<<<NCC, 128>>>(Wph, bp, out);
}

// round 14
// speedup vs baseline: 1.6844x; 1.6844x over previous
#include <cuda_runtime.h>
#include <cuda_bf16.h>
#include <math.h>
#include <stdint.h>

// Problem constants
#define BB 128     // batch
#define SS 256     // seq len
#define DD 512     // embed dim
#define HH 1024    // hidden
#define NCC 128    // num classes
#define NCLS 129   // embedding rows

// Recurrence config
#define RGRID 128      // persistent CTAs, each owns 8 h-cols (32 gate-cols)
#define RTHREADS 512   // 16 warps: four split-K quarters of 4 warps each
#define HCPC 8         // h-cols per CTA
#define NCPC 32        // gate-cols per CTA
#define HROW 2048      // bytes per h row (1024 bf16)

// SMEM: 16 resident weight tiles (32n x 64k bf16, 4KB, SW128)
//       8 A tiles (2 per k-quarter, 16KB each); D buffers (4 x 128 x 36 fp32) overlap A
#define W_TILE  4096
#define W_BYTES (16 * W_TILE)
#define A_TILE  16384
#define D_ROW   144
#define DBUF    (128 * D_ROW)
#define SMEM_DYN (W_BYTES + 8 * A_TILE + 1024)

#define SWZ(o) ((o) ^ (((o) >> 3) & 0x70))

// ---------------- device scratch ----------------
__device__ float d_P[(size_t)NCLS * HH * 4];     // P[class][col][gate]
__device__ float d_Wp[(size_t)HH * HH * 4];      // Wp[k][col][gate] fp32
__device__ int   d_xT[SS * BB];                  // x transposed [t][b]
__device__ __nv_bfloat16 d_hbf[2][BB * HH];      // h double buffer, [b][k] bf16
__device__ float d_hfin[BB * HH];                // final-step h fp32 [b][k]
__device__ unsigned d_bar_arrive = 0;
__device__ unsigned d_bar_gen = 0;

// ---------------- helpers ----------------
__device__ __forceinline__ uint32_t smem_u32(const void* p) {
    uint32_t a;
    asm("{ .reg .u64 t; cvta.to.shared.u64 t, %1; cvt.u32.u64 %0, t; }" : "=r"(a) : "l"(p));
    return a;
}
__device__ __forceinline__ void ldsm4(uint32_t& r0, uint32_t& r1, uint32_t& r2, uint32_t& r3,
                                      uint32_t addr) {
    asm volatile("ldmatrix.sync.aligned.m8n8.x4.shared.b16 {%0,%1,%2,%3}, [%4];"
                 : "=r"(r0), "=r"(r1), "=r"(r2), "=r"(r3) : "r"(addr));
}
__device__ __forceinline__ void mma16816(float* d, const uint32_t* a, uint32_t b0, uint32_t b1) {
    asm volatile("mma.sync.aligned.m16n8k16.row.col.f32.bf16.bf16.f32 "
                 "{%0,%1,%2,%3}, {%4,%5,%6,%7}, {%8,%9}, {%0,%1,%2,%3};"
                 : "+f"(d[0]), "+f"(d[1]), "+f"(d[2]), "+f"(d[3])
                 : "r"(a[0]), "r"(a[1]), "r"(a[2]), "r"(a[3]), "r"(b0), "r"(b1));
}
__device__ __forceinline__ float sigf(float x) {
    float e = __expf(-x);
    return __fdividef(1.0f, 1.0f + e);
}
__device__ __forceinline__ float tanh_s(float x) {
    float a = fabsf(x);
    float e = __expf(-2.0f * a);
    float r = __fdividef(1.0f - e, 1.0f + e);
    return copysignf(r, x);
}

// R12-proven atomic-generation grid barrier
__device__ __forceinline__ void grid_sync_all(unsigned G) {
    __threadfence();
    __syncthreads();
    if (threadIdx.x == 0) {
        unsigned gen = atomicAdd(&d_bar_gen, 0u);
        if (atomicAdd(&d_bar_arrive, 1u) == G - 1u) {
            atomicExch(&d_bar_arrive, 0u);
            __threadfence();
            atomicAdd(&d_bar_gen, 1u);
        } else {
            while (atomicAdd(&d_bar_gen, 0u) == gen) { }
        }
        __threadfence();
    }
    __syncthreads();
}

// load one A tile (h k-block kt: 128 rows x 64 bf16) into SMEM at dst (SW128);
// executed by the 128 threads of one k-quarter (gtid = 0..127)
__device__ __forceinline__ void load_tile(const char* hsrc, int kt, uint32_t dst, int gtid) {
#pragma unroll
    for (int j = 0; j < 8; j++) {
        const int g   = gtid + j * 128;           // 0..1023
        const int row = g >> 3, c16 = g & 7;
        const char* s = hsrc + (size_t)row * HROW + (size_t)kt * 128 + c16 * 16;
        uint32_t d = dst + SWZ((unsigned)(row * 128 + c16 * 16));
        asm volatile("cp.async.cg.shared.global [%0], [%1], 16;" :: "r"(d), "l"(s));
    }
}

// ---------------- prep kernels ----------------
__global__ void k_misc(const int* __restrict__ x) {
    int i = blockIdx.x * 256 + threadIdx.x;
    if (i < BB * HH / 2) ((uint32_t*)d_hbf)[i] = 0u;   // zero bf16 h buffer 0
    if (i < SS * BB) {
        int t = i >> 7, b = i & 127;
        d_xT[i] = x[b * SS + t];
    }
}

__global__ void k_pack(const float* __restrict__ Wfh, const float* __restrict__ Wih,
                       const float* __restrict__ Wgh, const float* __restrict__ Woh) {
    int i = blockIdx.x * 256 + threadIdx.x;
    if (i < HH * HH) {
        float4 v = make_float4(Wfh[i], Wih[i], Wgh[i], Woh[i]);
        *(float4*)(d_Wp + 4 * (size_t)i) = v;
    }
}

__global__ void k_precomp(const float* __restrict__ emb,
                          const float* __restrict__ Wfx, const float* __restrict__ Wix,
                          const float* __restrict__ Wgx, const float* __restrict__ Wox,
                          const float* __restrict__ bfv, const float* __restrict__ biv,
                          const float* __restrict__ bgv, const float* __restrict__ bov) {
    __shared__ float es[16][32];
    const int tid = threadIdx.x;
    const int col = blockIdx.x * 128 + tid;
    const int c0  = blockIdx.y * 16;

    float acc[16][4];
#pragma unroll
    for (int ci = 0; ci < 16; ci++)
#pragma unroll
        for (int g = 0; g < 4; g++) acc[ci][g] = 0.0f;

    for (int k0 = 0; k0 < DD; k0 += 32) {
        for (int q = tid; q < 16 * 32; q += 128) {
            int ci = q >> 5, kk = q & 31;
            int c = c0 + ci;
            es[ci][kk] = (c < NCLS) ? emb[(size_t)c * DD + k0 + kk] : 0.0f;
        }
        __syncthreads();
#pragma unroll 4
        for (int kk = 0; kk < 32; kk++) {
            int d = k0 + kk;
            float wf = Wfx[(size_t)d * HH + col];
            float wi = Wix[(size_t)d * HH + col];
            float wg = Wgx[(size_t)d * HH + col];
            float wo = Wox[(size_t)d * HH + col];
#pragma unroll
            for (int ci = 0; ci < 16; ci++) {
                float e = es[ci][kk];
                acc[ci][0] = fmaf(e, wf, acc[ci][0]);
                acc[ci][1] = fmaf(e, wi, acc[ci][1]);
                acc[ci][2] = fmaf(e, wg, acc[ci][2]);
                acc[ci][3] = fmaf(e, wo, acc[ci][3]);
            }
        }
        __syncthreads();
    }
    float b0v = bfv[col], b1v = biv[col], b2v = bgv[col], b3v = bov[col];
#pragma unroll
    for (int ci = 0; ci < 16; ci++) {
        int c = c0 + ci;
        if (c < NCLS) {
            float4 v = make_float4(acc[ci][0] + b0v, acc[ci][1] + b1v,
                                   acc[ci][2] + b2v, acc[ci][3] + b3v);
            *(float4*)(d_P + ((size_t)c * HH + col) * 4) = v;
        }
    }
}

// ---------------- persistent mma.sync recurrence (128 CTAs, 4-way split-K, 16 warps) ----------------
// CTA owns 32 gate-cols (8 h-cols). Weights SMEM-resident bf16 (SW128 tiles, 64KB).
// Warp group q (warps 4q..4q+3) owns k in [256q, 256q+256). Warp tile m64 x n16.
// Per quarter: 4 k64-tiles, 2 A buffers, wait->bar->load ordering (race-free with 2 bufs).
// Partial D sums in four SMEM buffers; 512-thread epilogue sums them (2 cols/thread).
__global__ void __launch_bounds__(RTHREADS, 1) k_recur() {
    extern __shared__ __align__(16) char dsm[];
    const int tid  = threadIdx.x;
    const int wid  = tid >> 5;
    const int lane = tid & 31;
    const int cta  = blockIdx.x;
    const int kq   = wid >> 2;        // 0..3 : k-quarter
    const int mw   = (wid >> 1) & 1;  // m64 half
    const int nw   = wid & 1;         // n16 half
    const int gtid = tid & 127;       // thread id within k-quarter

    uint32_t smem0 = smem_u32(dsm);
    uint32_t base  = (smem0 + 1023u) & ~1023u;
    char* dsb = dsm + (base - smem0);
    const uint32_t Wb = base;
    const uint32_t Ab = base + W_BYTES;
    char* dptr = dsb + W_BYTES;       // D buffers overlap A region (128KB >= 72KB)

    // ---- resident weights: tile q = k-block [64q, 64q+64); rows n=0..31, SW128
    for (int q = 0; q < 16; q++) {
        const float* src = d_Wp + (size_t)q * 64 * (HH * 4) + cta * NCPC;
        char* tile = dsb + q * W_TILE;
        for (int i2 = tid; i2 < 2048; i2 += RTHREADS) {
            int n = i2 & 31, kk = i2 >> 5;
            *(__nv_bfloat16*)(tile + SWZ((unsigned)(n * 128 + kk * 2))) =
                __float2bfloat16(src[(size_t)kk * (HH * 4) + n]);
        }
    }
    __syncthreads();

    // ---- lane-constant ldmatrix address pieces
    const int grp = lane >> 3, r8 = lane & 7;
    uint32_t a_row[4], a_xor[4];
#pragma unroll
    for (int mt = 0; mt < 4; mt++) {
        int m = 64 * mw + 16 * mt + (grp & 1) * 8 + r8;
        a_row[mt] = (uint32_t)(m * 128);
        a_xor[mt] = (uint32_t)((m & 7) * 16);
    }
    const int cgA = grp >> 1;
    // B: one ldsm.x4 per kc covers n16 x k16
    const int nB = 16 * nw + (grp >> 1) * 8 + r8;
    const uint32_t b_row = (uint32_t)(nB * 128);
    const uint32_t b_xor = (uint32_t)((nB & 7) * 16);
    const int cgB = grp & 1;

    // epilogue ownership: b = tid&127, col-pair = tid>>7 (2 cols each)
    const int eb   = tid & 127;
    const int epr  = tid >> 7;        // 0..3

    const int barid = 1 + kq;

    float C[2];
    C[0] = 0.0f; C[1] = 0.0f;

    for (int t = 0; t < SS; t++) {
        const char* hsrc = (const char*)d_hbf[t & 1];

        // preload this quarter's first k-tile
        load_tile(hsrc, 4 * kq + 0, Ab + (kq * 2 + 0) * A_TILE, gtid);
        asm volatile("cp.async.commit_group;");

        float acc[4][2][4];
#pragma unroll
        for (int mt = 0; mt < 4; mt++)
#pragma unroll
            for (int nt = 0; nt < 2; nt++)
#pragma unroll
                for (int e = 0; e < 4; e++) acc[mt][nt][e] = 0.0f;

        for (int i = 0; i < 4; i++) {
            asm volatile("cp.async.wait_group 0;");
            asm volatile("bar.sync %0, %1;" :: "r"(barid), "r"(128) : "memory");
            if (i < 3) {   // 2 buffers safe: tile i+1's buffer was consumed at iter i-1, synced above
                load_tile(hsrc, 4 * kq + i + 1, Ab + (kq * 2 + ((i + 1) & 1)) * A_TILE, gtid);
                asm volatile("cp.async.commit_group;");
            }
            const uint32_t Abuf  = Ab + (kq * 2 + (i & 1)) * A_TILE;
            const uint32_t Wtile = Wb + (4 * kq + i) * W_TILE;
#pragma unroll
            for (int kc = 0; kc < 4; kc++) {
                uint32_t a[4][4];
#pragma unroll
                for (int mt = 0; mt < 4; mt++)
                    ldsm4(a[mt][0], a[mt][1], a[mt][2], a[mt][3],
                          Abuf + a_row[mt] + (((unsigned)(16 * (2 * kc + cgA))) ^ a_xor[mt]));
                uint32_t bf[4];
                ldsm4(bf[0], bf[1], bf[2], bf[3],
                      Wtile + b_row + (((unsigned)(16 * (2 * kc + cgB))) ^ b_xor));
#pragma unroll
                for (int mt = 0; mt < 4; mt++) {
                    mma16816(acc[mt][0], a[mt], bf[0], bf[1]);
                    mma16816(acc[mt][1], a[mt], bf[2], bf[3]);
                }
            }
        }

        // full sync: no D write may start while any quarter still reads its A buffers
        __syncthreads();

        // ---- partial D -> SMEM (per k-quarter buffer)
        char* dD = dptr + kq * DBUF;
#pragma unroll
        for (int mt = 0; mt < 4; mt++) {
#pragma unroll
            for (int nt = 0; nt < 2; nt++) {
                int r0 = 64 * mw + 16 * mt + (lane >> 2);
                int cc = 16 * nw + 8 * nt + 2 * (lane & 3);
                *(float2*)(dD + r0 * D_ROW + cc * 4) =
                    make_float2(acc[mt][nt][0], acc[mt][nt][1]);
                *(float2*)(dD + (r0 + 8) * D_ROW + cc * 4) =
                    make_float2(acc[mt][nt][2], acc[mt][nt][3]);
            }
        }
        __syncthreads();

        // ---- epilogue: thread = (batch row, col-pair); sums four k-quarter partials
        const int cls = d_xT[t * BB + eb];
        const float4* Pp = (const float4*)(d_P + ((size_t)cls * HH + cta * HCPC + epr * 2) * 4);
        const char* drow = dptr + eb * D_ROW + epr * 32;
        __nv_bfloat16 hb16[2];
#pragma unroll
        for (int c = 0; c < 2; c++) {
            float4 d0 = *(const float4*)(drow + c * 16);
            float4 d1 = *(const float4*)(drow + DBUF + c * 16);
            float4 d2 = *(const float4*)(drow + 2 * DBUF + c * 16);
            float4 d3 = *(const float4*)(drow + 3 * DBUF + c * 16);
            float4 pg = Pp[c];
            float f  = sigf((d0.x + d1.x) + (d2.x + d3.x) + pg.x);
            float ii = sigf((d0.y + d1.y) + (d2.y + d3.y) + pg.y);
            float gg = sigf((d0.z + d1.z) + (d2.z + d3.z) + pg.z);
            float oo = sigf((d0.w + d1.w) + (d2.w + d3.w) + pg.w);
            float Cn = fmaf(gg, ii, C[c] * f);
            Cn = (cls > 0) ? Cn : 0.0f;
            C[c] = Cn;
            float hv = oo * tanh_s(Cn);
            hb16[c] = __float2bfloat16(hv);
            if (t == SS - 1) d_hfin[(size_t)eb * HH + cta * HCPC + epr * 2 + c] = hv;
        }
        __nv_bfloat16* hd = d_hbf[(t + 1) & 1] + (size_t)eb * HH + cta * HCPC + epr * 2;
        *(uint32_t*)hd = *(uint32_t*)&hb16[0];

        grid_sync_all(RGRID);
    }
}

// ---------------- head ----------------
__global__ void k_head(const float* __restrict__ Wph, const float* __restrict__ bp,
                       float* __restrict__ out) {
    __shared__ float h_s[HH];
    __shared__ float red[128];
    const int b = blockIdx.x;
    const int n = threadIdx.x;

    for (int i = n; i < HH; i += 128) h_s[i] = d_hfin[(size_t)b * HH + i];
    __syncthreads();

    float p = bp[n];
#pragma unroll 8
    for (int k = 0; k < HH; k++) p = fmaf(h_s[k], Wph[(size_t)k * NCC + n], p);

    red[n] = p;
    __syncthreads();
    for (int s = 64; s > 0; s >>= 1) {
        if (n < s) red[n] = fmaxf(red[n], red[n + s]);
        __syncthreads();
    }
    float mx = red[0];
    __syncthreads();
    red[n] = __expf(p - mx);
    __syncthreads();
    for (int s = 64; s > 0; s >>= 1) {
        if (n < s) red[n] += red[n + s];
        __syncthreads();
    }
    float lse = mx + logf(red[0]);
    out[(size_t)b * NCC + n] = p - lse;
}

// ---------------- launch ----------------
extern "C" void kernel_launch(void* const* d_in, const int* in_sizes, int n_in,
                              void* d_out, int out_size) {
    const int*   x   = (const int*)d_in[0];
    const float* emb = (const float*)d_in[1];
    const float* Wfx = (const float*)d_in[2];
    const float* Wfh = (const float*)d_in[3];
    const float* bf  = (const float*)d_in[4];
    const float* Wix = (const float*)d_in[5];
    const float* Wih = (const float*)d_in[6];
    const float* bi  = (const float*)d_in[7];
    const float* Wgx = (const float*)d_in[8];
    const float* Wgh = (const float*)d_in[9];
    const float* bg  = (const float*)d_in[10];
    const float* Wox = (const float*)d_in[11];
    const float* Woh = (const float*)d_in[12];
    const float* bo  = (const float*)d_in[13];
    const float* Wph = (const float*)d_in[14];
    const float* bp  = (const float*)d_in[15];
    float* out = (float*)d_out;

    cudaFuncSetAttribute(k_recur, cudaFuncAttributeMaxDynamicSharedMemorySize, SMEM_DYN);

    k_misc<<<512, 256>>>(x);
    k_pack<<<(HH * HH + 255) / 256, 256>>>(Wfh, Wih, Wgh, Woh);
    dim3 gP(8, 9);
    k_precomp<<<gP, 128>>>(emb, Wfx, Wix, Wgx, Wox, bf, bi, bg, bo);
    k_recur<<<RGRID, RTHREADS, SMEM_DYN>>>();
    k_head<<<NCC, 128>>>(Wph, bp, out);
}

// round 15
// speedup vs baseline: 1.7897x; 1.0626x over previous
#include <cuda_runtime.h>
#include <cuda_bf16.h>
#include <math.h>
#include <stdint.h>

// Problem constants
#define BB 128     // batch
#define SS 256     // seq len
#define DD 512     // embed dim
#define HH 1024    // hidden
#define NCC 128    // num classes
#define NCLS 129   // embedding rows

// Recurrence config
#define RGRID 128      // persistent CTAs, each owns 8 h-cols (32 gate-cols)
#define RTHREADS 256   // 8 warps: two split-K halves of 4 warps each
#define HCPC 8         // h-cols per CTA
#define NCPC 32        // gate-cols per CTA
#define HROW 2048      // bytes per h row (1024 bf16)

// SMEM: 16 resident weight tiles (32n x 64k bf16, 4KB, SW128)
//       6 A tiles (3 per k-half, 16KB each); D buffers (2 x 128 x 36 fp32) overlap A
#define W_TILE  4096
#define W_BYTES (16 * W_TILE)
#define A_TILE  16384
#define D_ROW   144
#define DBUF    (128 * D_ROW)
#define SMEM_DYN (W_BYTES + 6 * A_TILE + 1024)

#define SWZ(o) ((o) ^ (((o) >> 3) & 0x70))

// ---------------- device scratch ----------------
__device__ float d_P[(size_t)NCLS * HH * 4];     // P[class][col][gate]
__device__ float d_Wp[(size_t)HH * HH * 4];      // Wp[k][col][gate] fp32
__device__ int   d_xT[SS * BB];                  // x transposed [t][b]
__device__ __nv_bfloat16 d_hbf[2][BB * HH];      // h double buffer, [b][k] bf16
__device__ float d_hfin[BB * HH];                // final-step h fp32 [b][k]
// tree barrier state: 8 group counters on separate 128B lines, root, generation
__device__ unsigned d_bar_grp[8 * 32];
__device__ unsigned d_bar_root = 0;
__device__ unsigned d_bar_gen = 0;

// ---------------- helpers ----------------
__device__ __forceinline__ uint32_t smem_u32(const void* p) {
    uint32_t a;
    asm("{ .reg .u64 t; cvta.to.shared.u64 t, %1; cvt.u32.u64 %0, t; }" : "=r"(a) : "l"(p));
    return a;
}
__device__ __forceinline__ void ldsm4(uint32_t& r0, uint32_t& r1, uint32_t& r2, uint32_t& r3,
                                      uint32_t addr) {
    asm volatile("ldmatrix.sync.aligned.m8n8.x4.shared.b16 {%0,%1,%2,%3}, [%4];"
                 : "=r"(r0), "=r"(r1), "=r"(r2), "=r"(r3) : "r"(addr));
}
__device__ __forceinline__ void mma16816(float* d, const uint32_t* a, uint32_t b0, uint32_t b1) {
    asm volatile("mma.sync.aligned.m16n8k16.row.col.f32.bf16.bf16.f32 "
                 "{%0,%1,%2,%3}, {%4,%5,%6,%7}, {%8,%9}, {%0,%1,%2,%3};"
                 : "+f"(d[0]), "+f"(d[1]), "+f"(d[2]), "+f"(d[3])
                 : "r"(a[0]), "r"(a[1]), "r"(a[2]), "r"(a[3]), "r"(b0), "r"(b1));
}
__device__ __forceinline__ float sigf(float x) {
    float e = __expf(-x);
    return __fdividef(1.0f, 1.0f + e);
}
__device__ __forceinline__ float tanh_s(float x) {
    float a = fabsf(x);
    float e = __expf(-2.0f * a);
    float r = __fdividef(1.0f - e, 1.0f + e);
    return copysignf(r, x);
}
__device__ __forceinline__ unsigned ld_acq_u32(const unsigned* p) {
    unsigned v;
    asm volatile("ld.acquire.gpu.global.u32 %0, [%1];" : "=r"(v) : "l"(p) : "memory");
    return v;
}

// tree-arrive barrier, read-only release poll (no RMW storms)
__device__ __forceinline__ void grid_sync_all(int cta) {
    __threadfence();
    __syncthreads();
    if (threadIdx.x == 0) {
        unsigned gen = ld_acq_u32(&d_bar_gen);
        int g = cta >> 4;                 // 8 groups of 16 CTAs
        if (atomicAdd(&d_bar_grp[g * 32], 1u) == 15u) {
            if (atomicAdd(&d_bar_root, 1u) == 7u) {
#pragma unroll
                for (int j = 0; j < 8; j++) atomicExch(&d_bar_grp[j * 32], 0u);
                atomicExch(&d_bar_root, 0u);
                __threadfence();
                atomicAdd(&d_bar_gen, 1u);
            }
        }
        while (ld_acq_u32(&d_bar_gen) == gen) { }
    }
    __syncthreads();
}

// load one A tile (h k-block kt: 128 rows x 64 bf16) into SMEM at dst (SW128);
// executed by the 128 threads of one k-half (gtid = 0..127)
__device__ __forceinline__ void load_tile(const char* hsrc, int kt, uint32_t dst, int gtid) {
#pragma unroll
    for (int j = 0; j < 8; j++) {
        const int g   = gtid + j * 128;           // 0..1023
        const int row = g >> 3, c16 = g & 7;
        const char* s = hsrc + (size_t)row * HROW + (size_t)kt * 128 + c16 * 16;
        uint32_t d = dst + SWZ((unsigned)(row * 128 + c16 * 16));
        asm volatile("cp.async.cg.shared.global [%0], [%1], 16;" :: "r"(d), "l"(s));
    }
}

// ---------------- prep kernels ----------------
__global__ void k_misc(const int* __restrict__ x) {
    int i = blockIdx.x * 256 + threadIdx.x;
    if (i < BB * HH / 2) ((uint32_t*)d_hbf)[i] = 0u;   // zero bf16 h buffer 0
    if (i < SS * BB) {
        int t = i >> 7, b = i & 127;
        d_xT[i] = x[b * SS + t];
    }
}

__global__ void k_pack(const float* __restrict__ Wfh, const float* __restrict__ Wih,
                       const float* __restrict__ Wgh, const float* __restrict__ Woh) {
    int i = blockIdx.x * 256 + threadIdx.x;
    if (i < HH * HH) {
        float4 v = make_float4(Wfh[i], Wih[i], Wgh[i], Woh[i]);
        *(float4*)(d_Wp + 4 * (size_t)i) = v;
    }
}

__global__ void k_precomp(const float* __restrict__ emb,
                          const float* __restrict__ Wfx, const float* __restrict__ Wix,
                          const float* __restrict__ Wgx, const float* __restrict__ Wox,
                          const float* __restrict__ bfv, const float* __restrict__ biv,
                          const float* __restrict__ bgv, const float* __restrict__ bov) {
    __shared__ float es[16][32];
    const int tid = threadIdx.x;
    const int col = blockIdx.x * 128 + tid;
    const int c0  = blockIdx.y * 16;

    float acc[16][4];
#pragma unroll
    for (int ci = 0; ci < 16; ci++)
#pragma unroll
        for (int g = 0; g < 4; g++) acc[ci][g] = 0.0f;

    for (int k0 = 0; k0 < DD; k0 += 32) {
        for (int q = tid; q < 16 * 32; q += 128) {
            int ci = q >> 5, kk = q & 31;
            int c = c0 + ci;
            es[ci][kk] = (c < NCLS) ? emb[(size_t)c * DD + k0 + kk] : 0.0f;
        }
        __syncthreads();
#pragma unroll 4
        for (int kk = 0; kk < 32; kk++) {
            int d = k0 + kk;
            float wf = Wfx[(size_t)d * HH + col];
            float wi = Wix[(size_t)d * HH + col];
            float wg = Wgx[(size_t)d * HH + col];
            float wo = Wox[(size_t)d * HH + col];
#pragma unroll
            for (int ci = 0; ci < 16; ci++) {
                float e = es[ci][kk];
                acc[ci][0] = fmaf(e, wf, acc[ci][0]);
                acc[ci][1] = fmaf(e, wi, acc[ci][1]);
                acc[ci][2] = fmaf(e, wg, acc[ci][2]);
                acc[ci][3] = fmaf(e, wo, acc[ci][3]);
            }
        }
        __syncthreads();
    }
    float b0v = bfv[col], b1v = biv[col], b2v = bgv[col], b3v = bov[col];
#pragma unroll
    for (int ci = 0; ci < 16; ci++) {
        int c = c0 + ci;
        if (c < NCLS) {
            float4 v = make_float4(acc[ci][0] + b0v, acc[ci][1] + b1v,
                                   acc[ci][2] + b2v, acc[ci][3] + b3v);
            *(float4*)(d_P + ((size_t)c * HH + col) * 4) = v;
        }
    }
}

// ---------------- persistent mma.sync recurrence (128 CTAs, split-K, 8 warps) ----------------
// CTA owns 32 gate-cols (8 h-cols). Weights SMEM-resident bf16 (SW128 tiles, 64KB).
// Warps 0-3: k in [0,512); warps 4-7: k in [512,1024). Warp tile m64 x n16.
// Partial D sums in two SMEM buffers; 256-thread epilogue sums them.
__global__ void __launch_bounds__(RTHREADS, 1) k_recur() {
    extern __shared__ __align__(16) char dsm[];
    const int tid  = threadIdx.x;
    const int wid  = tid >> 5;
    const int lane = tid & 31;
    const int cta  = blockIdx.x;
    const int kw   = wid >> 2;        // 0..1 : k-half
    const int mw   = (wid >> 1) & 1;  // m64 half
    const int nw   = wid & 1;         // n16 half
    const int gtid = tid & 127;       // thread id within k-half

    uint32_t smem0 = smem_u32(dsm);
    uint32_t base  = (smem0 + 1023u) & ~1023u;
    char* dsb = dsm + (base - smem0);
    const uint32_t Wb = base;
    const uint32_t Ab = base + W_BYTES;
    char* dptr = dsb + W_BYTES;       // D buffers overlap A region (96KB >= 36KB)

    // ---- resident weights: tile q = k-block [64q, 64q+64); rows n=0..31, SW128
    for (int q = 0; q < 16; q++) {
        const float* src = d_Wp + (size_t)q * 64 * (HH * 4) + cta * NCPC;
        char* tile = dsb + q * W_TILE;
        for (int i2 = tid; i2 < 2048; i2 += RTHREADS) {
            int n = i2 & 31, kk = i2 >> 5;
            *(__nv_bfloat16*)(tile + SWZ((unsigned)(n * 128 + kk * 2))) =
                __float2bfloat16(src[(size_t)kk * (HH * 4) + n]);
        }
    }
    __syncthreads();

    // ---- lane-constant ldmatrix address pieces
    const int grp = lane >> 3, r8 = lane & 7;
    uint32_t a_row[4], a_xor[4];
#pragma unroll
    for (int mt = 0; mt < 4; mt++) {
        int m = 64 * mw + 16 * mt + (grp & 1) * 8 + r8;
        a_row[mt] = (uint32_t)(m * 128);
        a_xor[mt] = (uint32_t)((m & 7) * 16);
    }
    const int cgA = grp >> 1;
    // B: one ldsm.x4 per kc covers n16 x k16
    const int nB = 16 * nw + (grp >> 1) * 8 + r8;
    const uint32_t b_row = (uint32_t)(nB * 128);
    const uint32_t b_xor = (uint32_t)((nB & 7) * 16);
    const int cgB = grp & 1;

    // epilogue ownership: b = tid&127, col-quad = tid>>7 (4 cols each)
    const int eb   = tid & 127;
    const int ehal = tid >> 7;

    const int tb = kw * 3;            // A-buffer base index for this k-half
    const int barid = 1 + kw;

    float C[4];
#pragma unroll
    for (int c = 0; c < 4; c++) C[c] = 0.0f;

    for (int t = 0; t < SS; t++) {
        const char* hsrc = (const char*)d_hbf[t & 1];

        // prefetch epilogue operands (known at step start) to hide L2 latency
        const int cls = d_xT[t * BB + eb];
        const float4* PpG = (const float4*)(d_P + ((size_t)cls * HH + cta * HCPC + ehal * 4) * 4);
        float4 pg0 = PpG[0], pg1 = PpG[1], pg2 = PpG[2], pg3 = PpG[3];

        // preload this half's first two k-tiles
        load_tile(hsrc, 8 * kw + 0, Ab + (tb + 0) * A_TILE, gtid);
        asm volatile("cp.async.commit_group;");
        load_tile(hsrc, 8 * kw + 1, Ab + (tb + 1) * A_TILE, gtid);
        asm volatile("cp.async.commit_group;");

        float acc[4][2][4];
#pragma unroll
        for (int mt = 0; mt < 4; mt++)
#pragma unroll
            for (int nt = 0; nt < 2; nt++)
#pragma unroll
                for (int e = 0; e < 4; e++) acc[mt][nt][e] = 0.0f;

        for (int i = 0; i < 8; i++) {
            if (i < 7) asm volatile("cp.async.wait_group 1;");
            else       asm volatile("cp.async.wait_group 0;");
            asm volatile("bar.sync %0, %1;" :: "r"(barid), "r"(128) : "memory");
            if (i < 6) {
                load_tile(hsrc, 8 * kw + i + 2, Ab + (tb + (i + 2) % 3) * A_TILE, gtid);
                asm volatile("cp.async.commit_group;");
            }
            const uint32_t Abuf  = Ab + (tb + i % 3) * A_TILE;
            const uint32_t Wtile = Wb + (8 * kw + i) * W_TILE;
#pragma unroll
            for (int kc = 0; kc < 4; kc++) {
                uint32_t a[4][4];
#pragma unroll
                for (int mt = 0; mt < 4; mt++)
                    ldsm4(a[mt][0], a[mt][1], a[mt][2], a[mt][3],
                          Abuf + a_row[mt] + (((unsigned)(16 * (2 * kc + cgA))) ^ a_xor[mt]));
                uint32_t bf[4];
                ldsm4(bf[0], bf[1], bf[2], bf[3],
                      Wtile + b_row + (((unsigned)(16 * (2 * kc + cgB))) ^ b_xor));
#pragma unroll
                for (int mt = 0; mt < 4; mt++) {
                    mma16816(acc[mt][0], a[mt], bf[0], bf[1]);
                    mma16816(acc[mt][1], a[mt], bf[2], bf[3]);
                }
            }
        }

        // full sync: no D write may start while any half still reads its A buffers
        __syncthreads();

        // ---- partial D -> SMEM (per k-half buffer)
        char* dD = dptr + kw * DBUF;
#pragma unroll
        for (int mt = 0; mt < 4; mt++) {
#pragma unroll
            for (int nt = 0; nt < 2; nt++) {
                int r0 = 64 * mw + 16 * mt + (lane >> 2);
                int cc = 16 * nw + 8 * nt + 2 * (lane & 3);
                *(float2*)(dD + r0 * D_ROW + cc * 4) =
                    make_float2(acc[mt][nt][0], acc[mt][nt][1]);
                *(float2*)(dD + (r0 + 8) * D_ROW + cc * 4) =
                    make_float2(acc[mt][nt][2], acc[mt][nt][3]);
            }
        }
        __syncthreads();

        // ---- epilogue: thread = (batch row, col-quad); sums both k-half partials
        const char* drow = dptr + eb * D_ROW + ehal * 64;
        __nv_bfloat16 hb16[4];
        float4 pg[4] = {pg0, pg1, pg2, pg3};
#pragma unroll
        for (int c = 0; c < 4; c++) {
            float4 d0 = *(const float4*)(drow + c * 16);
            float4 d1 = *(const float4*)(drow + DBUF + c * 16);
            float f  = sigf(d0.x + d1.x + pg[c].x);
            float ii = sigf(d0.y + d1.y + pg[c].y);
            float gg = sigf(d0.z + d1.z + pg[c].z);
            float oo = sigf(d0.w + d1.w + pg[c].w);
            float Cn = fmaf(gg, ii, C[c] * f);
            Cn = (cls > 0) ? Cn : 0.0f;
            C[c] = Cn;
            float hv = oo * tanh_s(Cn);
            hb16[c] = __float2bfloat16(hv);
            if (t == SS - 1) d_hfin[(size_t)eb * HH + cta * HCPC + ehal * 4 + c] = hv;
        }
        __nv_bfloat16* hd = d_hbf[(t + 1) & 1] + (size_t)eb * HH + cta * HCPC + ehal * 4;
        *(uint2*)hd = *(uint2*)&hb16[0];

        grid_sync_all(cta);
    }
}

// ---------------- head ----------------
__global__ void k_head(const float* __restrict__ Wph, const float* __restrict__ bp,
                       float* __restrict__ out) {
    __shared__ float h_s[HH];
    __shared__ float red[128];
    const int b = blockIdx.x;
    const int n = threadIdx.x;

    for (int i = n; i < HH; i += 128) h_s[i] = d_hfin[(size_t)b * HH + i];
    __syncthreads();

    float p = bp[n];
#pragma unroll 8
    for (int k = 0; k < HH; k++) p = fmaf(h_s[k], Wph[(size_t)k * NCC + n], p);

    red[n] = p;
    __syncthreads();
    for (int s = 64; s > 0; s >>= 1) {
        if (n < s) red[n] = fmaxf(red[n], red[n + s]);
        __syncthreads();
    }
    float mx = red[0];
    __syncthreads();
    red[n] = __expf(p - mx);
    __syncthreads();
    for (int s = 64; s > 0; s >>= 1) {
        if (n < s) red[n] += red[n + s];
        __syncthreads();
    }
    float lse = mx + logf(red[0]);
    out[(size_t)b * NCC + n] = p - lse;
}

// ---------------- launch ----------------
extern "C" void kernel_launch(void* const* d_in, const int* in_sizes, int n_in,
                              void* d_out, int out_size) {
    const int*   x   = (const int*)d_in[0];
    const float* emb = (const float*)d_in[1];
    const float* Wfx = (const float*)d_in[2];
    const float* Wfh = (const float*)d_in[3];
    const float* bf  = (const float*)d_in[4];
    const float* Wix = (const float*)d_in[5];
    const float* Wih = (const float*)d_in[6];
    const float* bi  = (const float*)d_in[7];
    const float* Wgx = (const float*)d_in[8];
    const float* Wgh = (const float*)d_in[9];
    const float* bg  = (const float*)d_in[10];
    const float* Wox = (const float*)d_in[11];
    const float* Woh = (const float*)d_in[12];
    const float* bo  = (const float*)d_in[13];
    const float* Wph = (const float*)d_in[14];
    const float* bp  = (const float*)d_in[15];
    float* out = (float*)d_out;

    cudaFuncSetAttribute(k_recur, cudaFuncAttributeMaxDynamicSharedMemorySize, SMEM_DYN);

    k_misc<<<512, 256>>>(x);
    k_pack<<<(HH * HH + 255) / 256, 256>>>(Wfh, Wih, Wgh, Woh);
    dim3 gP(8, 9);
    k_precomp<<<gP, 128>>>(emb, Wfx, Wix, Wgx, Wox, bf, bi, bg, bo);
    k_recur<<<RGRID, RTHREADS, SMEM_DYN>>>();
    k_head<<<NCC, 128>>>(Wph, bp, out);
}